// round 13
// baseline (speedup 1.0000x reference)
#include <cuda_runtime.h>
#include <cuda_bf16.h>
#include <cfloat>
#include <cstdint>

// ================= static scratch =================
#define MAX_NF    15200000
#define MAX_LF    30400000
#define MAX_NODE  50048
#define MAX_F     304
#define KPAD      320
#define NPADW     384
#define APAD_ROWS 100096

__device__ float g_nodebuf[MAX_NF];
__device__ float g_outpre[MAX_NF];
__device__ float g_pq[MAX_LF];
__device__ float g_r[MAX_NF];
__device__ int   g_flags[MAX_NODE];
__device__ float g_sums[MAX_F],  g_sumsq[MAX_F];
__device__ float g_sums2[MAX_F], g_sumsq2[MAX_F];
__device__ float g_scale1[MAX_F], g_shift1[MAX_F];
__device__ float g_scale2[MAX_F], g_shift2[MAX_F];

__device__ __align__(16) __nv_bfloat16 g_Ah[(size_t)APAD_ROWS * KPAD];
__device__ __align__(16) __nv_bfloat16 g_Al[(size_t)APAD_ROWS * KPAD];
__device__ __align__(16) __nv_bfloat16 g_Wh[NPADW * KPAD];
__device__ __align__(16) __nv_bfloat16 g_Wl[NPADW * KPAD];

__device__ __forceinline__ uint32_t smem_u32(const void* p) {
    uint32_t a;
    asm("{ .reg .u64 t; cvta.to.shared.u64 t, %1; cvt.u32.u64 %0, t; }" : "=r"(a) : "l"(p));
    return a;
}
__device__ __forceinline__ void cp_async16(uint32_t saddr, const void* g) {
    asm volatile("cp.async.ca.shared.global [%0], [%1], 16;" :: "r"(saddr), "l"(g) : "memory");
}
#define CP_COMMIT() asm volatile("cp.async.commit_group;" ::: "memory")
#define CP_WAIT(n)  asm volatile("cp.async.wait_group %0;" :: "n"(n) : "memory")

// ================= small kernels =================
__global__ void k_init(const float* __restrict__ g1, int NCur, int F) {
    int total = NCur * F;
    int tid = blockIdx.x * blockDim.x + threadIdx.x;
    for (int idx = tid; idx < total; idx += gridDim.x * blockDim.x) {
        int f = idx % F;
        g_nodebuf[idx] = (g1[f] >= 0.f) ? 0.f : FLT_MAX;
    }
    if (tid < NCur) g_flags[tid] = 0;
    if (tid < F) { g_sums[tid]=0.f; g_sumsq[tid]=0.f; g_sums2[tid]=0.f; g_sumsq2[tid]=0.f; }
}

__global__ void k_flag(const int* __restrict__ cur_idx, int E) {
    int e = blockIdx.x * blockDim.x + threadIdx.x;
    if (e < E) g_flags[cur_idx[e]] = 1;
}

// row-based fp32 -> bf16 hi/lo split of [lastF | lastC]
__global__ __launch_bounds__(KPAD)
void k_convA_pq(const float* __restrict__ lastF, const float* __restrict__ lastC,
                int NLast, int F) {
    const int m = blockIdx.x;
    const int t = threadIdx.x;            // 0..319
    float v = 0.f;
    if (m < NLast) {
        if (t < F)          v = lastF[(size_t)m * F + t];
        else if (t < F + 3) v = lastC[m * 3 + (t - F)];
    }
    __nv_bfloat16 hi = __float2bfloat16(v);
    size_t idx = (size_t)m * KPAD + t;
    g_Ah[idx] = hi;
    g_Al[idx] = __float2bfloat16(v - __bfloat162float(hi));
}

__global__ void k_convW(const float* __restrict__ W, int Kvalid, int F) {
    int total = NPADW * KPAD;
    for (int idx = blockIdx.x * blockDim.x + threadIdx.x; idx < total;
         idx += gridDim.x * blockDim.x) {
        int n = idx / KPAD;
        int k = idx - n * KPAD;
        float v = (n < F && k < Kvalid) ? W[(size_t)k * F + n] : 0.f;
        __nv_bfloat16 hi = __float2bfloat16(v);
        g_Wh[idx] = hi;
        g_Wl[idx] = __float2bfloat16(v - __bfloat162float(hi));
    }
}

// row-based BN1(agg) -> bf16 hi/lo
__global__ __launch_bounds__(KPAD)
void k_convA_node(int NCur, int F) {
    const int n = blockIdx.x;
    const int t = threadIdx.x;
    float v = 0.f;
    if (n < NCur && t < F && g_flags[n])
        v = g_scale1[t] * g_nodebuf[(size_t)n * F + t] + g_shift1[t];
    __nv_bfloat16 hi = __float2bfloat16(v);
    size_t idx = (size_t)n * KPAD + t;
    g_Ah[idx] = hi;
    g_Al[idx] = __float2bfloat16(v - __bfloat162float(hi));
}

// R = curC @ W1c
__global__ void k_r(const float* __restrict__ curC, const float* __restrict__ W1,
                    int NCur, int F) {
    int total = NCur * F;
    for (int idx = blockIdx.x * blockDim.x + threadIdx.x; idx < total;
         idx += gridDim.x * blockDim.x) {
        int n = idx / F;
        int f = idx - n * F;
        float c0 = curC[n*3+0], c1 = curC[n*3+1], c2 = curC[n*3+2];
        g_r[idx] = c0 * W1[(size_t)(F+0) * F + f]
                 + c1 * W1[(size_t)(F+1) * F + f]
                 + c2 * W1[(size_t)(F+2) * F + f];
    }
}

// ================= edge stage: warp-per-edge, float2 slots =================
// lane owns slots s = lane+32k (k=0..4); features 2s, 2s+1 (masked at >=F).
#define EW_THREADS 256
__global__ __launch_bounds__(EW_THREADS)
void k_edge3(const int* __restrict__ cur_idx, const int* __restrict__ last_idx,
             const float* __restrict__ g1, int E, int F)
{
    __shared__ float sSum[2 * MAX_F];
    const int t    = threadIdx.x;
    const int lane = t & 31;
    const int nWarpsTotal = (gridDim.x * EW_THREADS) >> 5;
    const int gw = (blockIdx.x * EW_THREADS + t) >> 5;

    for (int i = t; i < 2 * MAX_F; i += EW_THREADS) sSum[i] = 0.f;

    float asum[10], asq[10];
    bool  act[10], pos[10];
#pragma unroll
    for (int k = 0; k < 5; ++k) {
        const int s  = lane + 32 * k;
        const int f0 = 2 * s, f1 = 2 * s + 1;
        act[2*k]   = (f0 < F);
        act[2*k+1] = (f1 < F);
        pos[2*k]   = act[2*k]   ? (g1[f0] >= 0.f) : true;
        pos[2*k+1] = act[2*k+1] ? (g1[f1] >= 0.f) : true;
        asum[2*k] = 0.f; asum[2*k+1] = 0.f; asq[2*k] = 0.f; asq[2*k+1] = 0.f;
    }
    __syncthreads();

    for (int e = gw; e < E; e += nWarpsTotal) {
        const int l = __ldg(&last_idx[e]);
        const int c = __ldg(&cur_idx[e]);
        const float2* __restrict__ pqrow = reinterpret_cast<const float2*>(&g_pq[(size_t)l * F]);
        const float2* __restrict__ rrow  = reinterpret_cast<const float2*>(&g_r [(size_t)c * F]);
        float2* __restrict__ nbrow = reinterpret_cast<float2*>(&g_nodebuf[(size_t)c * F]);

        float2 pq[5], rr[5], nb[5];
#pragma unroll
        for (int k = 0; k < 5; ++k) {
            const int s = lane + 32 * k;
            pq[k] = __ldg(&pqrow[s]);
            rr[k] = __ldg(&rrow[s]);
            nb[k] = nbrow[s];          // stale-tolerant precheck read
        }
#pragma unroll
        for (int k = 0; k < 5; ++k) {
            const int s = lane + 32 * k;
            const float z0 = fmaxf(pq[k].x - rr[k].x, 0.f);
            const float z1 = fmaxf(pq[k].y - rr[k].y, 0.f);
            if (act[2*k]) {
                asum[2*k] += z0; asq[2*k] += z0 * z0;
                int* a0 = (int*)&nbrow[s];
                const int zi0 = __float_as_int(z0);
                if (pos[2*k]) { if (zi0 > __float_as_int(nb[k].x)) atomicMax(a0, zi0); }
                else          { if (zi0 < __float_as_int(nb[k].x)) atomicMin(a0, zi0); }
            }
            if (act[2*k+1]) {
                asum[2*k+1] += z1; asq[2*k+1] += z1 * z1;
                int* a1 = ((int*)&nbrow[s]) + 1;
                const int zi1 = __float_as_int(z1);
                if (pos[2*k+1]) { if (zi1 > __float_as_int(nb[k].y)) atomicMax(a1, zi1); }
                else            { if (zi1 < __float_as_int(nb[k].y)) atomicMin(a1, zi1); }
            }
        }
    }

    // block-level stat reduction
#pragma unroll
    for (int k = 0; k < 5; ++k) {
        const int s = lane + 32 * k;
        if (act[2*k])   { atomicAdd(&sSum[2*s],       asum[2*k]);   atomicAdd(&sSum[MAX_F + 2*s],     asq[2*k]); }
        if (act[2*k+1]) { atomicAdd(&sSum[2*s+1],     asum[2*k+1]); atomicAdd(&sSum[MAX_F + 2*s + 1], asq[2*k+1]); }
    }
    __syncthreads();
    for (int f = t; f < F; f += EW_THREADS) {
        atomicAdd(&g_sums [f], sSum[f]);
        atomicAdd(&g_sumsq[f], sSum[MAX_F + f]);
    }
}

// ================= BN stats finalize =================
__global__ void k_stats(const float* __restrict__ g, const float* __restrict__ be,
                        float invN, int F, int which) {
    int f = blockIdx.x * blockDim.x + threadIdx.x;
    if (f >= F) return;
    float s  = which ? g_sums2[f]  : g_sums[f];
    float sq = which ? g_sumsq2[f] : g_sumsq[f];
    float mean = s * invN;
    float var  = fmaxf(sq * invN - mean * mean, 0.f);
    float rstd = rsqrtf(var + 1e-5f);
    float sc = g[f] * rstd;
    float sh = be[f] - mean * sc;
    if (which) { g_scale2[f] = sc; g_shift2[f] = sh; }
    else       { g_scale1[f] = sc; g_shift1[f] = sh; }
}

// ================= bf16-split HMMA GEMM, cp.async double-buffered =================
#define HM_NT 256
#define KC 64
#define SSTRIDE 72
#define TILE_B16 (128 * SSTRIDE)                 // 9216 bf16 = 18432 B
#define STAGE_B16 (4 * TILE_B16)                 // 4 buffers per stage
#define SMEM_HMMA_BYTES (2 * STAGE_B16 * 2)      // 147456 B

__device__ __forceinline__ void mma_bf16(float* d, const uint32_t* a, const uint32_t* b) {
    asm volatile(
        "mma.sync.aligned.m16n8k16.row.col.f32.bf16.bf16.f32 "
        "{%0,%1,%2,%3}, {%4,%5,%6,%7}, {%8,%9}, {%0,%1,%2,%3};"
        : "+f"(d[0]), "+f"(d[1]), "+f"(d[2]), "+f"(d[3])
        : "r"(a[0]), "r"(a[1]), "r"(a[2]), "r"(a[3]), "r"(b[0]), "r"(b[1]));
}

__global__ __launch_bounds__(HM_NT, 1)
void k_hmma(const float* __restrict__ bias, int Mvalid, int F, int mode)
{   // mode 0: +bias -> g_pq ; mode 1: relu+stats -> g_outpre
    const __nv_bfloat16* __restrict__ srcs[4] = { g_Ah, g_Al, g_Wh, g_Wl };
    float* __restrict__ outbuf = (mode == 0) ? g_pq : g_outpre;

    extern __shared__ __nv_bfloat16 sm[];
    const uint32_t smb = smem_u32(sm);

    const int t    = threadIdx.x;
    const int wid  = t >> 5;
    const int lane = t & 31;
    const int gr   = lane >> 2;
    const int tg   = lane & 3;
    const int wm   = wid & 3;
    const int wn   = wid >> 2;

    const int f0 = blockIdx.x * 128;   // fastest-varying -> A tile L2 reuse
    const int m0 = blockIdx.y * 128;
    const int rbase_[4] = { m0, m0, f0, f0 };

    float acc[2][8][4];
#pragma unroll
    for (int i = 0; i < 2; ++i)
#pragma unroll
        for (int j = 0; j < 8; ++j)
#pragma unroll
            for (int r = 0; r < 4; ++r) acc[i][j][r] = 0.f;

    auto load_chunk = [&](int c, int st) {
        const uint32_t sbase = smb + (uint32_t)st * STAGE_B16 * 2;
#pragma unroll
        for (int w = 0; w < 4; ++w) {
#pragma unroll
            for (int it = 0; it < 4; ++it) {
                int slot = it * HM_NT + t;
                int row = slot >> 3, q = slot & 7;
                uint32_t dst = sbase + (uint32_t)w * TILE_B16 * 2 + row * 144 + q * 16;
                cp_async16(dst, &srcs[w][(size_t)(rbase_[w] + row) * KPAD + c * KC + q * 8]);
            }
        }
        CP_COMMIT();
    };

    load_chunk(0, 0);

    const int NCH = KPAD / KC;   // 5
    for (int c = 0; c < NCH; ++c) {
        const int st = c & 1;
        if (c + 1 < NCH) { load_chunk(c + 1, st ^ 1); CP_WAIT(1); }
        else             { CP_WAIT(0); }
        __syncthreads();

        __nv_bfloat16* sAh = sm + st * STAGE_B16;
        __nv_bfloat16* sAl = sAh + TILE_B16;
        __nv_bfloat16* sBh = sAh + 2 * TILE_B16;
        __nv_bfloat16* sBl = sAh + 3 * TILE_B16;

#pragma unroll
        for (int kk = 0; kk < KC / 16; ++kk) {
            const int kb = kk * 16;
            uint32_t bh[8][2], bl[8][2];
#pragma unroll
            for (int na = 0; na < 8; ++na) {
                const int n = wn * 64 + na * 8 + gr;
                bh[na][0] = *reinterpret_cast<const uint32_t*>(&sBh[n * SSTRIDE + kb + tg * 2]);
                bh[na][1] = *reinterpret_cast<const uint32_t*>(&sBh[n * SSTRIDE + kb + 8 + tg * 2]);
                bl[na][0] = *reinterpret_cast<const uint32_t*>(&sBl[n * SSTRIDE + kb + tg * 2]);
                bl[na][1] = *reinterpret_cast<const uint32_t*>(&sBl[n * SSTRIDE + kb + 8 + tg * 2]);
            }
#pragma unroll
            for (int ma = 0; ma < 2; ++ma) {
                const int mr = wm * 32 + ma * 16 + gr;
                uint32_t ah[4], al[4];
                ah[0] = *reinterpret_cast<const uint32_t*>(&sAh[mr * SSTRIDE + kb + tg * 2]);
                ah[1] = *reinterpret_cast<const uint32_t*>(&sAh[(mr + 8) * SSTRIDE + kb + tg * 2]);
                ah[2] = *reinterpret_cast<const uint32_t*>(&sAh[mr * SSTRIDE + kb + 8 + tg * 2]);
                ah[3] = *reinterpret_cast<const uint32_t*>(&sAh[(mr + 8) * SSTRIDE + kb + 8 + tg * 2]);
                al[0] = *reinterpret_cast<const uint32_t*>(&sAl[mr * SSTRIDE + kb + tg * 2]);
                al[1] = *reinterpret_cast<const uint32_t*>(&sAl[(mr + 8) * SSTRIDE + kb + tg * 2]);
                al[2] = *reinterpret_cast<const uint32_t*>(&sAl[mr * SSTRIDE + kb + 8 + tg * 2]);
                al[3] = *reinterpret_cast<const uint32_t*>(&sAl[(mr + 8) * SSTRIDE + kb + 8 + tg * 2]);
#pragma unroll
                for (int na = 0; na < 8; ++na) {
                    mma_bf16(acc[ma][na], ah, bh[na]);
                    mma_bf16(acc[ma][na], ah, bl[na]);
                    mma_bf16(acc[ma][na], al, bh[na]);
                }
            }
        }
        __syncthreads();
    }

    // ---- epilogue ----
    float* sSum = (float*)sm;
    float* sSq  = (float*)sm + 128;
    if (mode == 1) {
        if (t < 128) { sSum[t] = 0.f; sSq[t] = 0.f; }
        __syncthreads();
    }

#pragma unroll
    for (int ma = 0; ma < 2; ++ma) {
#pragma unroll
        for (int na = 0; na < 8; ++na) {
            const int fc0 = wn * 64 + na * 8 + tg * 2;
            const int f_0 = f0 + fc0, f_1 = f_0 + 1;
            const int mA = m0 + wm * 32 + ma * 16 + gr;
            const int mB = mA + 8;
            float z0 = 0.f, z1 = 0.f, z2 = 0.f, z3 = 0.f;
            if (mode == 0) {
                if (f_0 < F) {
                    float b = bias[f_0];
                    if (mA < Mvalid) outbuf[(size_t)mA * F + f_0] = acc[ma][na][0] + b;
                    if (mB < Mvalid) outbuf[(size_t)mB * F + f_0] = acc[ma][na][2] + b;
                }
                if (f_1 < F) {
                    float b = bias[f_1];
                    if (mA < Mvalid) outbuf[(size_t)mA * F + f_1] = acc[ma][na][1] + b;
                    if (mB < Mvalid) outbuf[(size_t)mB * F + f_1] = acc[ma][na][3] + b;
                }
            } else {
                if (f_0 < F) {
                    float b = bias[f_0];
                    z0 = fmaxf(acc[ma][na][0] + b, 0.f);
                    z2 = fmaxf(acc[ma][na][2] + b, 0.f);
                    if (mA < Mvalid) outbuf[(size_t)mA * F + f_0] = z0; else z0 = 0.f;
                    if (mB < Mvalid) outbuf[(size_t)mB * F + f_0] = z2; else z2 = 0.f;
                }
                if (f_1 < F) {
                    float b = bias[f_1];
                    z1 = fmaxf(acc[ma][na][1] + b, 0.f);
                    z3 = fmaxf(acc[ma][na][3] + b, 0.f);
                    if (mA < Mvalid) outbuf[(size_t)mA * F + f_1] = z1; else z1 = 0.f;
                    if (mB < Mvalid) outbuf[(size_t)mB * F + f_1] = z3; else z3 = 0.f;
                }
                float s0 = z0 + z2, q0 = z0 * z0 + z2 * z2;
                float s1 = z1 + z3, q1 = z1 * z1 + z3 * z3;
#pragma unroll
                for (int off = 16; off >= 4; off >>= 1) {
                    s0 += __shfl_xor_sync(0xFFFFFFFFu, s0, off);
                    q0 += __shfl_xor_sync(0xFFFFFFFFu, q0, off);
                    s1 += __shfl_xor_sync(0xFFFFFFFFu, s1, off);
                    q1 += __shfl_xor_sync(0xFFFFFFFFu, q1, off);
                }
                if (gr == 0) {
                    atomicAdd(&sSum[fc0], s0);     atomicAdd(&sSq[fc0], q0);
                    atomicAdd(&sSum[fc0 + 1], s1); atomicAdd(&sSq[fc0 + 1], q1);
                }
            }
        }
    }
    if (mode == 1) {
        __syncthreads();
        if (t < 128) {
            int f = f0 + t;
            if (f < F) {
                atomicAdd(&g_sums2 [f], sSum[t]);
                atomicAdd(&g_sumsq2[f], sSq[t]);
            }
        }
    }
}

// ================= apply BN2 =================
__global__ void k_apply(float* __restrict__ out, int NCur, int F) {
    int total = NCur * F;
    for (int idx = blockIdx.x * blockDim.x + threadIdx.x; idx < total;
         idx += gridDim.x * blockDim.x) {
        int f = idx % F;
        out[idx] = g_scale2[f] * g_outpre[idx] + g_shift2[f];
    }
}

// ================= launch =================
extern "C" void kernel_launch(void* const* d_in, const int* in_sizes, int n_in,
                              void* d_out, int out_size) {
    const float* last_coors    = (const float*)d_in[0];
    const float* last_features = (const float*)d_in[1];
    const float* current_coors = (const float*)d_in[2];
    const int*   cur_idx       = (const int*)  d_in[3];
    const int*   last_idx      = (const int*)  d_in[4];
    const float* W1  = (const float*)d_in[5];
    const float* b1  = (const float*)d_in[6];
    const float* g1  = (const float*)d_in[7];
    const float* be1 = (const float*)d_in[8];
    const float* W2  = (const float*)d_in[9];
    const float* b2  = (const float*)d_in[10];
    const float* g2  = (const float*)d_in[11];
    const float* be2 = (const float*)d_in[12];

    const int F     = in_sizes[6];          // 300
    const int NCur  = in_sizes[2] / 3;      // 50000
    const int NLast = in_sizes[0] / 3;      // 100000
    const int E     = in_sizes[3];          // 500000
    float* out = (float*)d_out;

    cudaFuncSetAttribute(k_hmma, cudaFuncAttributeMaxDynamicSharedMemorySize, SMEM_HMMA_BYTES);

    const int mTilesPQ  = (NLast + 127) / 128;   // 782
    const int mTilesND  = (NCur + 127) / 128;    // 391
    const int nTiles    = (F + 127) / 128;       // 3

    {
        int total = NCur * F;
        k_init<<<(total + 255) / 256, 256>>>(g1, NCur, F);
    }
    k_flag<<<(E + 255) / 256, 256>>>(cur_idx, E);

    // --- PQ = [lastF|lastC] @ W1 + b1 via HMMA ---
    k_convA_pq<<<mTilesPQ * 128, KPAD>>>(last_features, last_coors, NLast, F);
    k_convW<<<(NPADW * KPAD + 255) / 256, 256>>>(W1, F + 3, F);
    {
        dim3 g(nTiles, mTilesPQ);   // f-tile fastest -> A L2 reuse
        k_hmma<<<g, HM_NT, SMEM_HMMA_BYTES>>>(b1, NLast, F, 0);
    }

    // --- R = curC @ W1c ---
    k_r<<<2048, 256>>>(current_coors, W1, NCur, F);

    // --- edge: warp-per-edge gather/sub/relu/scatter-max + BN1 stats ---
    k_edge3<<<148 * 4, EW_THREADS>>>(cur_idx, last_idx, g1, E, F);
    k_stats<<<(F + 255) / 256, 256>>>(g1, be1, 1.0f / (float)E, F, 0);

    // --- node GEMM ---
    k_convA_node<<<mTilesND * 128, KPAD>>>(NCur, F);
    k_convW<<<(NPADW * KPAD + 255) / 256, 256>>>(W2, F, F);
    {
        dim3 g(nTiles, mTilesND);
        k_hmma<<<g, HM_NT, SMEM_HMMA_BYTES>>>(b2, NCur, F, 1);
    }
    k_stats<<<(F + 255) / 256, 256>>>(g2, be2, 1.0f / (float)NCur, F, 1);

    k_apply<<<(NCur * F + 255) / 256, 256>>>(out, NCur, F);
}

// round 16
// speedup vs baseline: 1.2268x; 1.2268x over previous
#include <cuda_runtime.h>
#include <cuda_bf16.h>
#include <cfloat>
#include <cstdint>

// ================= static scratch =================
#define MAX_NF    15200000
#define MAX_LF    30400000
#define MAX_NODE  50048
#define MAX_F     304
#define KPAD      320
#define NPADW     384
#define APAD_ROWS 100096

__device__ float g_nodebuf[MAX_NF];
__device__ float g_outpre[MAX_NF];
__device__ float g_pq[MAX_LF];
__device__ float g_r[MAX_NF];
__device__ int   g_flags[MAX_NODE];
__device__ float g_sums[MAX_F],  g_sumsq[MAX_F];
__device__ float g_sums2[MAX_F], g_sumsq2[MAX_F];
__device__ float g_scale1[MAX_F], g_shift1[MAX_F];
__device__ float g_scale2[MAX_F], g_shift2[MAX_F];

__device__ __align__(16) __nv_bfloat16 g_Ah[(size_t)APAD_ROWS * KPAD];
__device__ __align__(16) __nv_bfloat16 g_Al[(size_t)APAD_ROWS * KPAD];
__device__ __align__(16) __nv_bfloat16 g_Wh[NPADW * KPAD];
__device__ __align__(16) __nv_bfloat16 g_Wl[NPADW * KPAD];

__device__ __forceinline__ uint32_t smem_u32(const void* p) {
    uint32_t a;
    asm("{ .reg .u64 t; cvta.to.shared.u64 t, %1; cvt.u32.u64 %0, t; }" : "=r"(a) : "l"(p));
    return a;
}
__device__ __forceinline__ void cp_async16(uint32_t saddr, const void* g) {
    asm volatile("cp.async.ca.shared.global [%0], [%1], 16;" :: "r"(saddr), "l"(g) : "memory");
}
#define CP_COMMIT() asm volatile("cp.async.commit_group;" ::: "memory")
#define CP_WAIT(n)  asm volatile("cp.async.wait_group %0;" :: "n"(n) : "memory")

// ================= small kernels =================
__global__ void k_init(const float* __restrict__ g1, int NCur, int F) {
    int total = NCur * F;
    int tid = blockIdx.x * blockDim.x + threadIdx.x;
    for (int idx = tid; idx < total; idx += gridDim.x * blockDim.x) {
        int f = idx % F;
        g_nodebuf[idx] = (g1[f] >= 0.f) ? 0.f : FLT_MAX;
    }
    if (tid < NCur) g_flags[tid] = 0;
    if (tid < F) { g_sums[tid]=0.f; g_sumsq[tid]=0.f; g_sums2[tid]=0.f; g_sumsq2[tid]=0.f; }
}

__global__ void k_flag(const int* __restrict__ cur_idx, int E) {
    int e = blockIdx.x * blockDim.x + threadIdx.x;
    if (e < E) g_flags[cur_idx[e]] = 1;
}

// row-based fp32 -> bf16 hi/lo split of [lastF | lastC]
__global__ __launch_bounds__(KPAD)
void k_convA_pq(const float* __restrict__ lastF, const float* __restrict__ lastC,
                int NLast, int F) {
    const int m = blockIdx.x;
    const int t = threadIdx.x;            // 0..319
    float v = 0.f;
    if (m < NLast) {
        if (t < F)          v = lastF[(size_t)m * F + t];
        else if (t < F + 3) v = lastC[m * 3 + (t - F)];
    }
    __nv_bfloat16 hi = __float2bfloat16(v);
    size_t idx = (size_t)m * KPAD + t;
    g_Ah[idx] = hi;
    g_Al[idx] = __float2bfloat16(v - __bfloat162float(hi));
}

__global__ void k_convW(const float* __restrict__ W, int Kvalid, int F) {
    int total = NPADW * KPAD;
    for (int idx = blockIdx.x * blockDim.x + threadIdx.x; idx < total;
         idx += gridDim.x * blockDim.x) {
        int n = idx / KPAD;
        int k = idx - n * KPAD;
        float v = (n < F && k < Kvalid) ? W[(size_t)k * F + n] : 0.f;
        __nv_bfloat16 hi = __float2bfloat16(v);
        g_Wh[idx] = hi;
        g_Wl[idx] = __float2bfloat16(v - __bfloat162float(hi));
    }
}

// row-based BN1(agg) -> bf16 hi/lo
__global__ __launch_bounds__(KPAD)
void k_convA_node(int NCur, int F) {
    const int n = blockIdx.x;
    const int t = threadIdx.x;
    float v = 0.f;
    if (n < NCur && t < F && g_flags[n])
        v = g_scale1[t] * g_nodebuf[(size_t)n * F + t] + g_shift1[t];
    __nv_bfloat16 hi = __float2bfloat16(v);
    size_t idx = (size_t)n * KPAD + t;
    g_Ah[idx] = hi;
    g_Al[idx] = __float2bfloat16(v - __bfloat162float(hi));
}

// R = curC @ W1c
__global__ void k_r(const float* __restrict__ curC, const float* __restrict__ W1,
                    int NCur, int F) {
    int total = NCur * F;
    for (int idx = blockIdx.x * blockDim.x + threadIdx.x; idx < total;
         idx += gridDim.x * blockDim.x) {
        int n = idx / F;
        int f = idx - n * F;
        float c0 = curC[n*3+0], c1 = curC[n*3+1], c2 = curC[n*3+2];
        g_r[idx] = c0 * W1[(size_t)(F+0) * F + f]
                 + c1 * W1[(size_t)(F+1) * F + f]
                 + c2 * W1[(size_t)(F+2) * F + f];
    }
}

// ================= edge stage (R9-proven: thread-per-feature) =================
#define ESB 256
#define ETHREADS 320
__global__ __launch_bounds__(ETHREADS)
void k_edge2(const int* __restrict__ cur_idx, const int* __restrict__ last_idx,
             const float* __restrict__ g1, int E, int F)
{
    __shared__ int sL[ESB], sC[ESB];
    const int t = threadIdx.x;
    const int f = t;
    const bool act = (f < F);
    const bool pos = act ? (g1[f] >= 0.f) : true;

    float ssum = 0.f, ssq = 0.f;

    for (int base = blockIdx.x * ESB; base < E; base += gridDim.x * ESB) {
        int cnt = min(ESB, E - base);
        __syncthreads();
        for (int i = t; i < cnt; i += ETHREADS) {
            sL[i] = last_idx[base + i];
            sC[i] = cur_idx[base + i];
        }
        __syncthreads();
        if (act) {
#pragma unroll 4
            for (int i = 0; i < cnt; ++i) {
                const float pq = __ldg(&g_pq[(size_t)sL[i] * F + f]);
                const float r  = __ldg(&g_r [(size_t)sC[i] * F + f]);
                const float z  = fmaxf(pq - r, 0.f);
                ssum += z; ssq += z * z;
                int* addr = (int*)&g_nodebuf[(size_t)sC[i] * F + f];
                const int zi = __float_as_int(z);
                const int cur = *((volatile int*)addr);
                if (pos) { if (zi > cur) atomicMax(addr, zi); }
                else     { if (zi < cur) atomicMin(addr, zi); }
            }
        }
    }
    if (act) {
        atomicAdd(&g_sums [f], ssum);
        atomicAdd(&g_sumsq[f], ssq);
    }
}

// ================= BN stats finalize =================
__global__ void k_stats(const float* __restrict__ g, const float* __restrict__ be,
                        float invN, int F, int which) {
    int f = blockIdx.x * blockDim.x + threadIdx.x;
    if (f >= F) return;
    float s  = which ? g_sums2[f]  : g_sums[f];
    float sq = which ? g_sumsq2[f] : g_sumsq[f];
    float mean = s * invN;
    float var  = fmaxf(sq * invN - mean * mean, 0.f);
    float rstd = rsqrtf(var + 1e-5f);
    float sc = g[f] * rstd;
    float sh = be[f] - mean * sc;
    if (which) { g_scale2[f] = sc; g_shift2[f] = sh; }
    else       { g_scale1[f] = sc; g_shift1[f] = sh; }
}

// ================= bf16-split HMMA GEMM, cp.async double-buffered =================
#define HM_NT 256
#define KC 64
#define SSTRIDE 72
#define TILE_B16 (128 * SSTRIDE)                 // 9216 bf16 = 18432 B
#define STAGE_B16 (4 * TILE_B16)
#define SMEM_HMMA_BYTES (2 * STAGE_B16 * 2)      // 147456 B

__device__ __forceinline__ void mma_bf16(float* d, const uint32_t* a, const uint32_t* b) {
    asm volatile(
        "mma.sync.aligned.m16n8k16.row.col.f32.bf16.bf16.f32 "
        "{%0,%1,%2,%3}, {%4,%5,%6,%7}, {%8,%9}, {%0,%1,%2,%3};"
        : "+f"(d[0]), "+f"(d[1]), "+f"(d[2]), "+f"(d[3])
        : "r"(a[0]), "r"(a[1]), "r"(a[2]), "r"(a[3]), "r"(b[0]), "r"(b[1]));
}

__global__ __launch_bounds__(HM_NT, 1)
void k_hmma(const float* __restrict__ bias, int Mvalid, int F, int mode)
{   // mode 0: +bias -> g_pq ; mode 1: relu+stats -> g_outpre
    const __nv_bfloat16* __restrict__ srcs[4] = { g_Ah, g_Al, g_Wh, g_Wl };
    float* __restrict__ outbuf = (mode == 0) ? g_pq : g_outpre;

    extern __shared__ __nv_bfloat16 sm[];
    const uint32_t smb = smem_u32(sm);

    const int t    = threadIdx.x;
    const int wid  = t >> 5;
    const int lane = t & 31;
    const int gr   = lane >> 2;
    const int tg   = lane & 3;
    const int wm   = wid & 3;
    const int wn   = wid >> 2;

    const int f0 = blockIdx.x * 128;   // fastest-varying -> A tile L2 reuse
    const int m0 = blockIdx.y * 128;
    const int rbase_[4] = { m0, m0, f0, f0 };

    float acc[2][8][4];
#pragma unroll
    for (int i = 0; i < 2; ++i)
#pragma unroll
        for (int j = 0; j < 8; ++j)
#pragma unroll
            for (int r = 0; r < 4; ++r) acc[i][j][r] = 0.f;

    auto load_chunk = [&](int c, int st) {
        const uint32_t sbase = smb + (uint32_t)st * STAGE_B16 * 2;
#pragma unroll
        for (int w = 0; w < 4; ++w) {
#pragma unroll
            for (int it = 0; it < 4; ++it) {
                int slot = it * HM_NT + t;
                int row = slot >> 3, q = slot & 7;
                uint32_t dst = sbase + (uint32_t)w * TILE_B16 * 2 + row * 144 + q * 16;
                cp_async16(dst, &srcs[w][(size_t)(rbase_[w] + row) * KPAD + c * KC + q * 8]);
            }
        }
        CP_COMMIT();
    };

    load_chunk(0, 0);

    const int NCH = KPAD / KC;   // 5
    for (int c = 0; c < NCH; ++c) {
        const int st = c & 1;
        if (c + 1 < NCH) { load_chunk(c + 1, st ^ 1); CP_WAIT(1); }
        else             { CP_WAIT(0); }
        __syncthreads();

        __nv_bfloat16* sAh = sm + st * STAGE_B16;
        __nv_bfloat16* sAl = sAh + TILE_B16;
        __nv_bfloat16* sBh = sAh + 2 * TILE_B16;
        __nv_bfloat16* sBl = sAh + 3 * TILE_B16;

#pragma unroll
        for (int kk = 0; kk < KC / 16; ++kk) {
            const int kb = kk * 16;
            uint32_t bh[8][2], bl[8][2];
#pragma unroll
            for (int na = 0; na < 8; ++na) {
                const int n = wn * 64 + na * 8 + gr;
                bh[na][0] = *reinterpret_cast<const uint32_t*>(&sBh[n * SSTRIDE + kb + tg * 2]);
                bh[na][1] = *reinterpret_cast<const uint32_t*>(&sBh[n * SSTRIDE + kb + 8 + tg * 2]);
                bl[na][0] = *reinterpret_cast<const uint32_t*>(&sBl[n * SSTRIDE + kb + tg * 2]);
                bl[na][1] = *reinterpret_cast<const uint32_t*>(&sBl[n * SSTRIDE + kb + 8 + tg * 2]);
            }
#pragma unroll
            for (int ma = 0; ma < 2; ++ma) {
                const int mr = wm * 32 + ma * 16 + gr;
                uint32_t ah[4], al[4];
                ah[0] = *reinterpret_cast<const uint32_t*>(&sAh[mr * SSTRIDE + kb + tg * 2]);
                ah[1] = *reinterpret_cast<const uint32_t*>(&sAh[(mr + 8) * SSTRIDE + kb + tg * 2]);
                ah[2] = *reinterpret_cast<const uint32_t*>(&sAh[mr * SSTRIDE + kb + 8 + tg * 2]);
                ah[3] = *reinterpret_cast<const uint32_t*>(&sAh[(mr + 8) * SSTRIDE + kb + 8 + tg * 2]);
                al[0] = *reinterpret_cast<const uint32_t*>(&sAl[mr * SSTRIDE + kb + tg * 2]);
                al[1] = *reinterpret_cast<const uint32_t*>(&sAl[(mr + 8) * SSTRIDE + kb + tg * 2]);
                al[2] = *reinterpret_cast<const uint32_t*>(&sAl[mr * SSTRIDE + kb + 8 + tg * 2]);
                al[3] = *reinterpret_cast<const uint32_t*>(&sAl[(mr + 8) * SSTRIDE + kb + 8 + tg * 2]);
#pragma unroll
                for (int na = 0; na < 8; ++na) {
                    mma_bf16(acc[ma][na], ah, bh[na]);
                    mma_bf16(acc[ma][na], ah, bl[na]);
                    mma_bf16(acc[ma][na], al, bh[na]);
                }
            }
        }
        __syncthreads();
    }

    // ---- epilogue ----
    float* sSum = (float*)sm;
    float* sSq  = (float*)sm + 128;
    if (mode == 1) {
        if (t < 128) { sSum[t] = 0.f; sSq[t] = 0.f; }
        __syncthreads();
    }

#pragma unroll
    for (int ma = 0; ma < 2; ++ma) {
#pragma unroll
        for (int na = 0; na < 8; ++na) {
            const int fc0 = wn * 64 + na * 8 + tg * 2;
            const int f_0 = f0 + fc0, f_1 = f_0 + 1;
            const int mA = m0 + wm * 32 + ma * 16 + gr;
            const int mB = mA + 8;
            float z0 = 0.f, z1 = 0.f, z2 = 0.f, z3 = 0.f;
            if (mode == 0) {
                if (f_0 < F) {
                    float b = bias[f_0];
                    if (mA < Mvalid) outbuf[(size_t)mA * F + f_0] = acc[ma][na][0] + b;
                    if (mB < Mvalid) outbuf[(size_t)mB * F + f_0] = acc[ma][na][2] + b;
                }
                if (f_1 < F) {
                    float b = bias[f_1];
                    if (mA < Mvalid) outbuf[(size_t)mA * F + f_1] = acc[ma][na][1] + b;
                    if (mB < Mvalid) outbuf[(size_t)mB * F + f_1] = acc[ma][na][3] + b;
                }
            } else {
                if (f_0 < F) {
                    float b = bias[f_0];
                    z0 = fmaxf(acc[ma][na][0] + b, 0.f);
                    z2 = fmaxf(acc[ma][na][2] + b, 0.f);
                    if (mA < Mvalid) outbuf[(size_t)mA * F + f_0] = z0; else z0 = 0.f;
                    if (mB < Mvalid) outbuf[(size_t)mB * F + f_0] = z2; else z2 = 0.f;
                }
                if (f_1 < F) {
                    float b = bias[f_1];
                    z1 = fmaxf(acc[ma][na][1] + b, 0.f);
                    z3 = fmaxf(acc[ma][na][3] + b, 0.f);
                    if (mA < Mvalid) outbuf[(size_t)mA * F + f_1] = z1; else z1 = 0.f;
                    if (mB < Mvalid) outbuf[(size_t)mB * F + f_1] = z3; else z3 = 0.f;
                }
                float s0 = z0 + z2, q0 = z0 * z0 + z2 * z2;
                float s1 = z1 + z3, q1 = z1 * z1 + z3 * z3;
#pragma unroll
                for (int off = 16; off >= 4; off >>= 1) {
                    s0 += __shfl_xor_sync(0xFFFFFFFFu, s0, off);
                    q0 += __shfl_xor_sync(0xFFFFFFFFu, q0, off);
                    s1 += __shfl_xor_sync(0xFFFFFFFFu, s1, off);
                    q1 += __shfl_xor_sync(0xFFFFFFFFu, q1, off);
                }
                if (gr == 0) {
                    atomicAdd(&sSum[fc0], s0);     atomicAdd(&sSq[fc0], q0);
                    atomicAdd(&sSum[fc0 + 1], s1); atomicAdd(&sSq[fc0 + 1], q1);
                }
            }
        }
    }
    if (mode == 1) {
        __syncthreads();
        if (t < 128) {
            int f = f0 + t;
            if (f < F) {
                atomicAdd(&g_sums2 [f], sSum[t]);
                atomicAdd(&g_sumsq2[f], sSq[t]);
            }
        }
    }
}

// ================= apply BN2 =================
__global__ void k_apply(float* __restrict__ out, int NCur, int F) {
    int total = NCur * F;
    for (int idx = blockIdx.x * blockDim.x + threadIdx.x; idx < total;
         idx += gridDim.x * blockDim.x) {
        int f = idx % F;
        out[idx] = g_scale2[f] * g_outpre[idx] + g_shift2[f];
    }
}

// ================= launch =================
extern "C" void kernel_launch(void* const* d_in, const int* in_sizes, int n_in,
                              void* d_out, int out_size) {
    const float* last_coors    = (const float*)d_in[0];
    const float* last_features = (const float*)d_in[1];
    const float* current_coors = (const float*)d_in[2];
    const int*   cur_idx       = (const int*)  d_in[3];
    const int*   last_idx      = (const int*)  d_in[4];
    const float* W1  = (const float*)d_in[5];
    const float* b1  = (const float*)d_in[6];
    const float* g1  = (const float*)d_in[7];
    const float* be1 = (const float*)d_in[8];
    const float* W2  = (const float*)d_in[9];
    const float* b2  = (const float*)d_in[10];
    const float* g2  = (const float*)d_in[11];
    const float* be2 = (const float*)d_in[12];

    const int F     = in_sizes[6];          // 300
    const int NCur  = in_sizes[2] / 3;      // 50000
    const int NLast = in_sizes[0] / 3;      // 100000
    const int E     = in_sizes[3];          // 500000
    float* out = (float*)d_out;

    cudaFuncSetAttribute(k_hmma, cudaFuncAttributeMaxDynamicSharedMemorySize, SMEM_HMMA_BYTES);

    const int mTilesPQ  = (NLast + 127) / 128;   // 782
    const int mTilesND  = (NCur + 127) / 128;    // 391
    const int nTiles    = (F + 127) / 128;       // 3

    {
        int total = NCur * F;
        k_init<<<(total + 255) / 256, 256>>>(g1, NCur, F);
    }
    k_flag<<<(E + 255) / 256, 256>>>(cur_idx, E);

    // --- PQ = [lastF|lastC] @ W1 + b1 via HMMA ---
    k_convA_pq<<<mTilesPQ * 128, KPAD>>>(last_features, last_coors, NLast, F);
    k_convW<<<(NPADW * KPAD + 255) / 256, 256>>>(W1, F + 3, F);
    {
        dim3 g(nTiles, mTilesPQ);   // f-tile fastest -> A L2 reuse
        k_hmma<<<g, HM_NT, SMEM_HMMA_BYTES>>>(b1, NLast, F, 0);
    }

    // --- R = curC @ W1c ---
    k_r<<<2048, 256>>>(current_coors, W1, NCur, F);

    // --- edge: thread-per-feature gather/sub/relu/scatter-max + BN1 stats ---
    k_edge2<<<148 * 8, ETHREADS>>>(cur_idx, last_idx, g1, E, F);
    k_stats<<<(F + 255) / 256, 256>>>(g1, be1, 1.0f / (float)E, F, 0);

    // --- node GEMM ---
    k_convA_node<<<mTilesND * 128, KPAD>>>(NCur, F);
    k_convW<<<(NPADW * KPAD + 255) / 256, 256>>>(W2, F, F);
    {
        dim3 g(nTiles, mTilesND);
        k_hmma<<<g, HM_NT, SMEM_HMMA_BYTES>>>(b2, NCur, F, 1);
    }
    k_stats<<<(F + 255) / 256, 256>>>(g2, be2, 1.0f / (float)NCur, F, 1);

    k_apply<<<(NCur * F + 255) / 256, 256>>>(out, NCur, F);
}